// round 8
// baseline (speedup 1.0000x reference)
#include <cuda_runtime.h>
#include <cstdint>

// Problem dims
#define B_   512
#define T_   1024
#define D_   64
#define H_   256
#define O_   64

#define ROWS 4
#define NCTA (B_/ROWS)     // 128 CTAs
#define NTHR 256
#define NCHUNK 80          // 16 x-chunks + 64 h-chunks (4 k each)
#define NSMEMC 54          // chunks resident in SMEM (x:16 + h:38)
#define NSTRC  (NCHUNK-NSMEMC)  // 26 streamed from L2
#define RING   5
#define HP 264             // padded h row stride (floats): r*264%32 = 8r -> distinct bank quads
#define XP 72              // padded x row stride

// Packed weights: [c][jj][g][kk]  (c=chunk, jj=j&3, g=j>>2 in 0..63, kk=k&3)
__device__ float g_W2[NCHUNK*1024];   // 320 KB

// fma.rn.f32x2 — packed dual fp32 FMA
__device__ __forceinline__ unsigned long long fma2(unsigned long long a,
                                                   unsigned long long b,
                                                   unsigned long long c) {
    unsigned long long d;
    asm("fma.rn.f32x2 %0, %1, %2, %3;" : "=l"(d) : "l"(a), "l"(b), "l"(c));
    return d;
}

// Repack Wf[H, D+H] into g_W2[c*1024 + jj*256 + g*4 + kk]
__global__ void ltc_prep_kernel(const float* __restrict__ Wf) {
    int i = blockIdx.x * blockDim.x + threadIdx.x;
    if (i >= NCHUNK*1024) return;
    int c   = i >> 10;
    int rem = i & 1023;
    int jj  = rem >> 8;
    int g   = (rem >> 2) & 63;
    int kk  = i & 3;
    int j   = g * 4 + jj;
    int k   = c * 4 + kk;                      // combined K index 0..319
    int col = (c < 16) ? k : (D_ + (k - D_));  // x part then h part (k>=64 -> col = k)
    g_W2[i] = Wf[j * (D_ + H_) + col];
}

// SMEM floats: w 54*1024 + h 2*4*HP + x 2*4*XP
#define SMEM_FLOATS (NSMEMC*1024 + 2*ROWS*HP + 2*ROWS*XP)

__global__ __launch_bounds__(NTHR, 1)
void ltc_main_kernel(const float* __restrict__ x,
                     const float* __restrict__ bf,
                     const float* __restrict__ tau,
                     const float* __restrict__ A,
                     const float* __restrict__ Wo,
                     const float* __restrict__ bo,
                     float* __restrict__ out)
{
    extern __shared__ float sm[];
    float* s_w = sm;                        // [54][1024]
    float* s_h = sm + NSMEMC*1024;          // [2][4][HP]
    float* s_x = s_h + 2*ROWS*HP;           // [2][4][XP]

    const int tid  = threadIdx.x;
    const int warp = tid >> 5;
    const int lane = tid & 31;
    const int r    = lane & 3;              // row this thread computes
    const int g    = (warp << 3) + (lane >> 2);  // j-group 0..63
    const int j0   = g << 2;                // first of 4 owned j's
    const int row0 = blockIdx.x * ROWS;

    // ---- stage SMEM-resident weights (coalesced float4) ----
    {
        float4*       dw = reinterpret_cast<float4*>(s_w);
        const float4* sw = reinterpret_cast<const float4*>(g_W2);
        for (int i = tid; i < (NSMEMC*1024)/4; i += NTHR) dw[i] = sw[i];
    }

    // ---- init state ----
    for (int i = tid; i < ROWS*HP; i += NTHR) s_h[i] = 0.0f;

    const int rx = tid >> 6, dx = tid & 63;
    const float* xrow = x + (size_t)(row0 + rx) * T_ * D_ + dx;
    s_x[rx*XP + dx] = xrow[0];

    const float4 bf4 = *reinterpret_cast<const float4*>(bf + j0);
    float4 tv = *reinterpret_cast<const float4*>(tau + j0);
    const float it0 = 1.0f/expf(tv.x), it1 = 1.0f/expf(tv.y),
                it2 = 1.0f/expf(tv.z), it3 = 1.0f/expf(tv.w);
    const float4 A4  = *reinterpret_cast<const float4*>(A + j0);
    float hreg[4] = {0.f, 0.f, 0.f, 0.f};

    const float* gwst = g_W2 + NSMEMC*1024;   // streamed chunk base
    const int goff = g << 2;

    __syncthreads();

    // ================= recurrent loop =================
    for (int t = 0; t < T_; ++t) {
        const float* hb = s_h + (t & 1) * (ROWS*HP);
        const float* xb = s_x + (t & 1) * (ROWS*XP);
        float*       hn = s_h + ((t + 1) & 1) * (ROWS*HP);
        float*       xn = s_x + ((t + 1) & 1) * (ROWS*XP);

        // kick off streamed-w ring (consumed after SMEM section, ~2000+ cyc later)
        ulonglong2 ring[RING][4];
#pragma unroll
        for (int p = 0; p < RING; p++)
#pragma unroll
            for (int jj = 0; jj < 4; jj++)
                ring[p][jj] = *reinterpret_cast<const ulonglong2*>(
                    gwst + p*1024 + jj*256 + goff);

        float x_next = 0.0f;
        if (t + 1 < T_) x_next = xrow[(t + 1) * D_];

        unsigned long long acc[4] = {0ull, 0ull, 0ull, 0ull};

        // ---- x section: chunks 0..15, v from x buffer ----
#pragma unroll
        for (int c = 0; c < 16; c++) {
            ulonglong2 v = *reinterpret_cast<const ulonglong2*>(xb + r*XP + (c << 2));
#pragma unroll
            for (int jj = 0; jj < 4; jj++) {
                ulonglong2 w = *reinterpret_cast<const ulonglong2*>(
                    s_w + (c << 10) + (jj << 8) + goff);
                acc[jj] = fma2(w.x, v.x, acc[jj]);
                acc[jj] = fma2(w.y, v.y, acc[jj]);
            }
        }

        // ---- h section (SMEM): chunks 16..53, v from h buffer ----
#pragma unroll
        for (int c = 16; c < NSMEMC; c++) {
            const int kh = c - 16;
            ulonglong2 v = *reinterpret_cast<const ulonglong2*>(hb + r*HP + (kh << 2));
#pragma unroll
            for (int jj = 0; jj < 4; jj++) {
                ulonglong2 w = *reinterpret_cast<const ulonglong2*>(
                    s_w + (c << 10) + (jj << 8) + goff);
                acc[jj] = fma2(w.x, v.x, acc[jj]);
                acc[jj] = fma2(w.y, v.y, acc[jj]);
            }
        }

        // ---- h section (L2-streamed): chunks 54..79 ----
#pragma unroll
        for (int cp = 0; cp < NSTRC; cp++) {
            const int kh = (NSMEMC - 16) + cp;   // 38..63
            ulonglong2 v = *reinterpret_cast<const ulonglong2*>(hb + r*HP + (kh << 2));
#pragma unroll
            for (int jj = 0; jj < 4; jj++) {
                ulonglong2 w = ring[cp % RING][jj];
                acc[jj] = fma2(w.x, v.x, acc[jj]);
                acc[jj] = fma2(w.y, v.y, acc[jj]);
            }
            if (cp + RING < NSTRC) {
#pragma unroll
                for (int jj = 0; jj < 4; jj++)
                    ring[cp % RING][jj] = *reinterpret_cast<const ulonglong2*>(
                        gwst + (cp + RING)*1024 + jj*256 + goff);
            }
        }

        // ---- gate + state update (4 j's, one row) ----
        float zb[4] = {bf4.x, bf4.y, bf4.z, bf4.w};
        float it[4] = {it0, it1, it2, it3};
        float Av[4] = {A4.x, A4.y, A4.z, A4.w};
        float hout[4];
#pragma unroll
        for (int jj = 0; jj < 4; jj++) {
            unsigned long long a = acc[jj];
            float z = __uint_as_float((unsigned)a)
                    + __uint_as_float((unsigned)(a >> 32)) + zb[jj];
            float e = __expf(-z);
            float f = __fdividef(1.0f, 1.0f + e);
            float h = hreg[jj];
            h += (-(it[jj] + f) * h + f * Av[jj]) * 0.1f;
            hreg[jj] = h;
            hout[jj] = h;
        }
        *reinterpret_cast<float4*>(hn + r*HP + j0) =
            make_float4(hout[0], hout[1], hout[2], hout[3]);
        xn[rx*XP + dx] = x_next;
        __syncthreads();
    }

    // ================= output projection =================
    {
        const float* hf = s_h + (T_ & 1) * (ROWS*HP);
        const int rr = tid >> 6, o = tid & 63;
        const float4* wo4 = reinterpret_cast<const float4*>(Wo + o*H_);
        const float4* hf4 = reinterpret_cast<const float4*>(hf + rr*HP);
        float s = 0.0f;
#pragma unroll
        for (int q = 0; q < H_/4; q++) {
            float4 w = wo4[q];
            float4 h = hf4[q];
            s += w.x*h.x + w.y*h.y + w.z*h.z + w.w*h.w;
        }
        out[(row0 + rr)*O_ + o] = s + bo[o];
    }
}

extern "C" void kernel_launch(void* const* d_in, const int* in_sizes, int n_in,
                              void* d_out, int out_size)
{
    (void)in_sizes; (void)n_in; (void)out_size;
    const float* x   = (const float*)d_in[0];
    const float* Wf  = (const float*)d_in[1];
    const float* bf  = (const float*)d_in[2];
    const float* tau = (const float*)d_in[3];
    const float* A   = (const float*)d_in[4];
    const float* Wo  = (const float*)d_in[5];
    const float* bo  = (const float*)d_in[6];
    float* out = (float*)d_out;

    const int smem_bytes = SMEM_FLOATS * (int)sizeof(float);  // 231,936 B
    cudaFuncSetAttribute(ltc_main_kernel,
                         cudaFuncAttributeMaxDynamicSharedMemorySize, smem_bytes);

    ltc_prep_kernel<<<(NCHUNK*1024 + NTHR - 1) / NTHR, NTHR>>>(Wf);
    ltc_main_kernel<<<NCTA, NTHR, smem_bytes>>>(x, bf, tau, A, Wo, bo, out);
}

// round 9
// speedup vs baseline: 1.0492x; 1.0492x over previous
#include <cuda_runtime.h>
#include <cstdint>

// Problem dims
#define B_   512
#define T_   1024
#define D_   64
#define H_   256
#define O_   64
#define KTOT 320          // combined [x(64) | h(256)]

#define ROWS 4
#define NCTA (B_/ROWS)    // 128
#define NTHR 512
#define NKB  8            // k-slices
#define KSL  40           // k per slice
#define VS   164          // padded slice stride (floats): kb*164 %32 = 4*kb -> distinct bank quads
#define RSTR (NKB*VS)     // 1312 floats per row
#define VBUF (ROWS*RSTR)  // 5248 floats per buffer

typedef unsigned long long ull;

// Per-thread packed weights: g_Wp2[p*512 + tid], p in [0,80)
__device__ ull g_Wp2[80*NTHR];   // 320 KB

__device__ __forceinline__ ull fma2(ull a, ull b, ull c) {
    ull d; asm("fma.rn.f32x2 %0, %1, %2, %3;" : "=l"(d) : "l"(a), "l"(b), "l"(c));
    return d;
}
__device__ __forceinline__ ull add2(ull a, ull b) {
    ull d; asm("add.rn.f32x2 %0, %1, %2;" : "=l"(d) : "l"(a), "l"(b));
    return d;
}

// Pack Wf[H, D+H] (cols = [x | h] concatenated = combined k) into per-thread layout.
__global__ void ltc_prep(const float* __restrict__ Wf) {
    int idx = blockIdx.x * blockDim.x + threadIdx.x;
    if (idx >= 80*NTHR) return;
    int p    = idx >> 9;
    int tid  = idx & 511;
    int warp = tid >> 5, lane = tid & 31;
    int kb   = lane & 7;
    int g    = warp * 4 + (lane >> 3);
    int jj   = p / 20, kp = p % 20;
    int j    = g * 4 + jj;
    int k    = kb * KSL + 2 * kp;
    float lo = Wf[j * KTOT + k];
    float hi = Wf[j * KTOT + k + 1];
    g_Wp2[p * NTHR + tid] = ((ull)__float_as_uint(hi) << 32) | __float_as_uint(lo);
}

// SMEM floats: v double buffer | z (ull[1024] = 2048 floats) | Wo staged (64 x 260)
#define SM_Z   (2*VBUF)
#define SM_WO  (SM_Z + 2048)
#define SM_TOT (SM_WO + 64*260)   // 29184 floats = 116736 B

__global__ __launch_bounds__(NTHR, 1)
void ltc_main(const float* __restrict__ x,
              const float* __restrict__ bf,
              const float* __restrict__ tau,
              const float* __restrict__ A,
              const float* __restrict__ Wo,
              const float* __restrict__ bo,
              float* __restrict__ out)
{
    extern __shared__ float sm[];
    float* s_v  = sm;
    ull*   s_z  = (ull*)(sm + SM_Z);
    float* s_wo = sm + SM_WO;

    const int tid  = threadIdx.x;
    const int lane = tid & 31;
    const int kb   = lane & 7;
    const int row0 = blockIdx.x * ROWS;

    // ---- weights to registers (coalesced LDG.64) ----
    ull w2[80];
#pragma unroll
    for (int p = 0; p < 80; p++) w2[p] = g_Wp2[p * NTHR + tid];

    // ---- update-thread persistent state: thread owns (j=uj, rows rr and rr+2) ----
    const int uj = tid & 255;
    const int rr = tid >> 8;
    const float bfj = bf[uj];
    const float itj = expf(-tau[uj]);     // 1/exp(tau)
    const float Aj  = A[uj];
    float h_a = 0.f, h_b = 0.f;
    const int hadr = ((64 + uj) / 40) * VS + (64 + uj) % 40;

    // ---- x-writer mapping (threads < 256) ----
    const int xr = (tid >> 6) & 3, xd = tid & 63;
    const float* xptr = x + (size_t)(row0 + xr) * T_ * D_ + xd;
    const int xadr = (xd / 40) * VS + xd % 40;

    // ---- init v[0]: zeros (h part) then x at t=0 ----
    for (int i = tid; i < VBUF; i += NTHR) s_v[i] = 0.f;
    __syncthreads();
    if (tid < 256) s_v[xr * RSTR + xadr] = xptr[0];
    __syncthreads();

    const int j0 = ((tid >> 5) * 4 + (lane >> 3)) * 4;  // first owned j

    // ================= recurrent loop =================
    for (int t = 0; t < T_; ++t) {
        const float* vb = s_v + (t & 1) * VBUF;
        float*       vn = s_v + ((t + 1) & 1) * VBUF;

        float x_pre = 0.f;
        if (tid < 256 && t + 1 < T_) x_pre = xptr[(t + 1) * D_];

        ull acc[16];
#pragma unroll
        for (int i = 0; i < 16; i++) acc[i] = 0ull;

        const float* vbk = vb + kb * VS;
#pragma unroll
        for (int q = 0; q < 10; q++) {
            ulonglong2 v0 = *(const ulonglong2*)(vbk + 0*RSTR + 4*q);
            ulonglong2 v1 = *(const ulonglong2*)(vbk + 1*RSTR + 4*q);
            ulonglong2 v2 = *(const ulonglong2*)(vbk + 2*RSTR + 4*q);
            ulonglong2 v3 = *(const ulonglong2*)(vbk + 3*RSTR + 4*q);
#pragma unroll
            for (int jj = 0; jj < 4; jj++) {
                ull wa = w2[jj*20 + 2*q], wb = w2[jj*20 + 2*q + 1];
                acc[jj*4+0] = fma2(wa, v0.x, acc[jj*4+0]);
                acc[jj*4+0] = fma2(wb, v0.y, acc[jj*4+0]);
                acc[jj*4+1] = fma2(wa, v1.x, acc[jj*4+1]);
                acc[jj*4+1] = fma2(wb, v1.y, acc[jj*4+1]);
                acc[jj*4+2] = fma2(wa, v2.x, acc[jj*4+2]);
                acc[jj*4+2] = fma2(wb, v2.y, acc[jj*4+2]);
                acc[jj*4+3] = fma2(wa, v3.x, acc[jj*4+3]);
                acc[jj*4+3] = fma2(wb, v3.y, acc[jj*4+3]);
            }
        }

        // ---- butterfly reduce across the 8 kb lanes (packed f32x2) ----
#pragma unroll
        for (int dd = 1; dd < 8; dd <<= 1) {
#pragma unroll
            for (int i = 0; i < 16; i++)
                acc[i] = add2(acc[i], __shfl_xor_sync(0xFFFFFFFFu, acc[i], dd));
        }

        // kb==0 lanes post raw dot products (still packed, no bias)
        if ((lane & 7) == 0) {
#pragma unroll
            for (int jj = 0; jj < 4; jj++)
#pragma unroll
                for (int r = 0; r < 4; r++)
                    s_z[r*256 + j0 + jj] = acc[jj*4 + r];
        }
        __syncthreads();

        // ---- gate + state update: thread (uj, rows rr / rr+2) ----
        {
            ull za = s_z[rr*256 + uj];
            ull zb = s_z[(rr+2)*256 + uj];
            float zA = __uint_as_float((unsigned)za)
                     + __uint_as_float((unsigned)(za >> 32)) + bfj;
            float zB = __uint_as_float((unsigned)zb)
                     + __uint_as_float((unsigned)(zb >> 32)) + bfj;
            float fA = __fdividef(1.f, 1.f + __expf(-zA));
            float fB = __fdividef(1.f, 1.f + __expf(-zB));
            h_a += (-(itj + fA) * h_a + fA * Aj) * 0.1f;
            h_b += (-(itj + fB) * h_b + fB * Aj) * 0.1f;
            vn[rr*RSTR + hadr]     = h_a;
            vn[(rr+2)*RSTR + hadr] = h_b;
            if (tid < 256) vn[xr*RSTR + xadr] = x_pre;
        }
        __syncthreads();
    }

    // ================= output projection =================
    // Linearize final h (held in update-thread registers) and stage Wo in SMEM.
    float* s_hl = (float*)s_z;                 // reuse as float[1024] = [r][j]
    s_hl[rr*256 + uj]     = h_a;
    s_hl[(rr+2)*256 + uj] = h_b;
    for (int i = tid; i < 64*256; i += NTHR) { // Wo[o][j] -> padded [o][260]
        int o = i >> 8, q = i & 255;
        s_wo[o*260 + q] = Wo[i];
    }
    __syncthreads();

    if (tid < 256) {
        int r = tid >> 6, o = tid & 63;
        const float4* w4 = (const float4*)(s_wo + o*260);
        const float4* h4 = (const float4*)(s_hl + r*256);
        float s = bo[o];
#pragma unroll
        for (int q = 0; q < 64; q++) {
            float4 w = w4[q];
            float4 h = h4[q];
            s += w.x*h.x + w.y*h.y + w.z*h.z + w.w*h.w;
        }
        out[(row0 + r)*O_ + o] = s;
    }
}

extern "C" void kernel_launch(void* const* d_in, const int* in_sizes, int n_in,
                              void* d_out, int out_size)
{
    (void)in_sizes; (void)n_in; (void)out_size;
    const float* x   = (const float*)d_in[0];
    const float* Wf  = (const float*)d_in[1];
    const float* bf  = (const float*)d_in[2];
    const float* tau = (const float*)d_in[3];
    const float* A   = (const float*)d_in[4];
    const float* Wo  = (const float*)d_in[5];
    const float* bo  = (const float*)d_in[6];
    float* out = (float*)d_out;

    const int smem_bytes = SM_TOT * (int)sizeof(float);  // 116,736 B
    cudaFuncSetAttribute(ltc_main,
                         cudaFuncAttributeMaxDynamicSharedMemorySize, smem_bytes);

    ltc_prep<<<(80*NTHR + NTHR - 1) / NTHR, NTHR>>>(Wf);
    ltc_main<<<NCTA, NTHR, smem_bytes>>>(x, bf, tau, A, Wo, bo, out);
}